// round 11
// baseline (speedup 1.0000x reference)
#include <cuda_runtime.h>
#include <cuda_fp16.h>
#include <cstdint>

// ---------------------------------------------------------------------------
// TernaryConv2d via mma.sync m16n8k16 (HMMA fp16, fp32 accum) implicit GEMM.
// Ternary weights exact in fp16 => only error is fp16(x) rounding (~2e-4).
// 512-thr CTA, 4 output rows (2x A amortization), 3-stage cp.async pipeline.
// x: [32,128,56,56] f32, w: [256,128,3,3] f32, bias:[256] -> out:[32,256,54,54]
// ---------------------------------------------------------------------------

#define CC    128
#define HHH   56
#define WID   56
#define OCH   256
#define OHH   54
#define OWW   54
#define NN    32

#define NTHR   512
#define ICK    16           // ic per chunk (one k16 HMMA deep)
#define NCHUNK 8
#define BROWS  6            // 4 out rows + 2 halo
#define BCOLS  68           // row stride in half2 words (56 data + pad)
#define PLX    424          // per-icpair plane stride (424%32=8 -> banks 8*t4+g: perm)
#define A_WORDS_CHUNK (9 * 8 * 32 * 4)         // 9216 words (half2) = 36864 B
#define A_BYTES_CHUNK (A_WORDS_CHUNK * 4)
#define B_WORDS       (8 * PLX)                // 3392 words = 13568 B
#define STAGE_BYTES   (A_BYTES_CHUNK + B_WORDS * 4)    // 50432
#define NSTAGE 3
#define SMEM_DYN      (NSTAGE * STAGE_BYTES)           // 151296

__device__ __align__(16) uint32_t g_qw[2 * NCHUNK * A_WORDS_CHUNK];  // 147456 words
__device__ __align__(16) uint32_t g_xh[NN * 64 * HHH * WID];         // half2 planes
__device__ unsigned g_wmax_bits;

// ------------------------- preprocessing ----------------------------------
__global__ void k_init() { g_wmax_bits = 0u; }

__global__ void k_max(const float* __restrict__ w, int n) {
    float m = 0.f;
    for (int i = blockIdx.x * blockDim.x + threadIdx.x; i < n; i += gridDim.x * blockDim.x)
        m = fmaxf(m, fabsf(w[i]));
#pragma unroll
    for (int o = 16; o > 0; o >>= 1) m = fmaxf(m, __shfl_xor_sync(~0u, m, o));
    __shared__ float sm[32];
    int lane = threadIdx.x & 31, wd = threadIdx.x >> 5;
    if (lane == 0) sm[wd] = m;
    __syncthreads();
    if (threadIdx.x < 32) {
        int nw = (blockDim.x + 31) >> 5;
        m = (threadIdx.x < nw) ? sm[threadIdx.x] : 0.f;
#pragma unroll
        for (int o = 16; o > 0; o >>= 1) m = fmaxf(m, __shfl_xor_sync(~0u, m, o));
        if (threadIdx.x == 0) atomicMax(&g_wmax_bits, __float_as_uint(m));
    }
}

// quantize weights into m16n8k16 A-fragment order, half2-packed:
// word idx = ((half*8+chunk)*72 + tap*8 + mtile)*128 + lane*4 + r
__global__ void k_quant(const float* __restrict__ w) {
    int idx = blockIdx.x * blockDim.x + threadIdx.x;
    if (idx >= 2 * NCHUNK * A_WORDS_CHUNK) return;
    int r     = idx & 3;
    int lane  = (idx >> 2) & 31;
    int f     = idx >> 7;
    int mtile = f & 7;
    int tap   = (f >> 3) % 9;
    int hc    = f / 72;
    int half  = hc >> 3, chunk = hc & 7;
    int g  = lane >> 2, t4 = lane & 3;
    int oc  = half * 128 + mtile * 16 + g + 8 * (r & 1);
    int ic0 = chunk * ICK + 2 * t4 + 8 * (r >> 1);
    float t = 0.05f * __uint_as_float(g_wmax_bits);
    float w0 = w[(oc * CC + ic0) * 9 + tap];
    float w1 = w[(oc * CC + ic0 + 1) * 9 + tap];
    __half h0 = __float2half_rn((w0 > t ? 1.f : 0.f) - (w0 < -t ? 1.f : 0.f));
    __half h1 = __float2half_rn((w1 > t ? 1.f : 0.f) - (w1 < -t ? 1.f : 0.f));
    g_qw[idx] = (uint32_t)__half_as_ushort(h0) | ((uint32_t)__half_as_ushort(h1) << 16);
}

// x -> channel-pair packed half2 planes, vectorized 4 cols/thread:
// g_xh[((n*64+icp)*56 + h)*56 + col]
__global__ void k_xh(const float* __restrict__ x) {
    int idx = blockIdx.x * blockDim.x + threadIdx.x;   // over NN*64*HHH*14
    if (idx >= NN * 64 * HHH * 14) return;
    int c4  = idx % 14;
    int h   = (idx / 14) % HHH;
    int icp = (idx / (14 * HHH)) & 63;
    int n   = idx / (14 * HHH * 64);
    const float* p = x + ((size_t)(n * CC + icp * 2) * HHH + h) * WID + c4 * 4;
    float4 a = *(const float4*)p;
    float4 b = *(const float4*)(p + HHH * WID);
    uint4 o;
    o.x = (uint32_t)__half_as_ushort(__float2half_rn(a.x)) | ((uint32_t)__half_as_ushort(__float2half_rn(b.x)) << 16);
    o.y = (uint32_t)__half_as_ushort(__float2half_rn(a.y)) | ((uint32_t)__half_as_ushort(__float2half_rn(b.y)) << 16);
    o.z = (uint32_t)__half_as_ushort(__float2half_rn(a.z)) | ((uint32_t)__half_as_ushort(__float2half_rn(b.z)) << 16);
    o.w = (uint32_t)__half_as_ushort(__float2half_rn(a.w)) | ((uint32_t)__half_as_ushort(__float2half_rn(b.w)) << 16);
    *(uint4*)(g_xh + ((size_t)(n * 64 + icp) * HHH + h) * WID + c4 * 4) = o;
}

// ------------------------- helpers -----------------------------------------
__device__ __forceinline__ void mma16(float* c, const uint4& a, uint32_t b0, uint32_t b1) {
    asm volatile(
        "mma.sync.aligned.m16n8k16.row.col.f32.f16.f16.f32 "
        "{%0,%1,%2,%3}, {%4,%5,%6,%7}, {%8,%9}, {%0,%1,%2,%3};"
        : "+f"(c[0]), "+f"(c[1]), "+f"(c[2]), "+f"(c[3])
        : "r"(a.x), "r"(a.y), "r"(a.z), "r"(a.w), "r"(b0), "r"(b1));
}

__device__ __forceinline__ uint32_t smem_u32(const void* p) {
    uint32_t a;
    asm("{ .reg .u64 t; cvta.to.shared.u64 t, %1; cvt.u32.u64 %0, t; }" : "=r"(a) : "l"(p));
    return a;
}

__device__ __forceinline__ void cpa16(uint32_t dst, const void* src) {
    asm volatile("cp.async.cg.shared.global [%0], [%1], 16;" :: "r"(dst), "l"(src) : "memory");
}
// zero-fill variant: src_size=0 writes zeros (for out-of-range rows)
__device__ __forceinline__ void cpa16_p(uint32_t dst, const void* src, int sz) {
    asm volatile("cp.async.cg.shared.global [%0], [%1], 16, %2;"
                 :: "r"(dst), "l"(src), "r"(sz) : "memory");
}

// issue all cp.async for one ic-chunk into stage buffer at smem addr `sbase`
__device__ __forceinline__ void stage_chunk(uint32_t sbase, int chunk, int half,
                                            int rg, int n, int tid) {
    // A: 2304 x 16B, linear (4.5 per thread)
    const uint4* asrc = (const uint4*)(g_qw + (size_t)(half * NCHUNK + chunk) * A_WORDS_CHUNK);
#pragma unroll
    for (int i = 0; i < 5; i++) {
        int e = i * NTHR + tid;
        if (e < A_WORDS_CHUNK / 4) cpa16(sbase + e * 16, asrc + e);
    }
    // B: 8 icpair x 6 rows x 14 x 16B; zero-fill rows beyond input (rg=13)
    const uint32_t bdst = sbase + A_BYTES_CHUNK;
#pragma unroll
    for (int it = 0; it < 2; it++) {
        int i = it * NTHR + tid;
        if (i < 8 * BROWS * 14) {
            int c4  = i % 14;
            int row = (i / 14) % BROWS;
            int icp = i / (14 * BROWS);
            int h   = rg * 4 + row;
            const uint32_t* s = g_xh + ((size_t)(n * 64 + chunk * 8 + icp) * HHH + h) * WID + c4 * 4;
            cpa16_p(bdst + (icp * PLX + row * BCOLS + c4 * 4) * 4, s, (h < HHH) ? 16 : 0);
        }
    }
    asm volatile("cp.async.commit_group;" ::: "memory");
}

// ------------------------- conv kernel --------------------------------------
// grid (2 oc-halves, 14 row-groups, 32 n), block 512 (warp_m 0..3, warp_n 0..3)
__global__ __launch_bounds__(NTHR, 1) void k_conv(const float* __restrict__ bias,
                                                  float* __restrict__ out) {
    extern __shared__ char smem[];
    const uint32_t sb = smem_u32(smem);

    const int tid    = threadIdx.x;
    const int wid    = tid >> 5;
    const int lane   = tid & 31;
    const int warp_m = wid & 3;
    const int warp_n = wid >> 2;      // 0..3 output rows
    const int g      = lane >> 2;
    const int t4     = lane & 3;
    const int half   = blockIdx.x;
    const int rg     = blockIdx.y;
    const int n      = blockIdx.z;

    // one-time zero of all B regions (pad cols 56..67 + plane pad stay zero)
    for (int s = 0; s < NSTAGE; s++) {
        uint32_t* B = (uint32_t*)(smem + s * STAGE_BYTES + A_BYTES_CHUNK);
        for (int i = tid; i < B_WORDS; i += NTHR) B[i] = 0;
    }
    __syncthreads();

    float acc[2][7][4];
#pragma unroll
    for (int mi = 0; mi < 2; mi++)
#pragma unroll
        for (int ni = 0; ni < 7; ni++)
#pragma unroll
            for (int r = 0; r < 4; r++) acc[mi][ni][r] = 0.f;

    stage_chunk(sb, 0, half, rg, n, tid);
    stage_chunk(sb + STAGE_BYTES, 1, half, rg, n, tid);

    for (int chunk = 0; chunk < NCHUNK; chunk++) {
        if (chunk + 1 < NCHUNK)
            asm volatile("cp.async.wait_group 1;" ::: "memory");
        else
            asm volatile("cp.async.wait_group 0;" ::: "memory");
        __syncthreads();
        if (chunk + 2 < NCHUNK)
            stage_chunk(sb + ((chunk + 2) % NSTAGE) * STAGE_BYTES, chunk + 2, half, rg, n, tid);

        const char*     stg = smem + (chunk % NSTAGE) * STAGE_BYTES;
        const uint4*    Af  = (const uint4*)stg;
        const uint32_t* Bs  = (const uint32_t*)(stg + A_BYTES_CHUNK);
        const uint32_t* Bq0 = Bs + t4 * PLX;          // k pair t4   (ic 2t4,2t4+1)
        const uint32_t* Bq1 = Bs + (t4 + 4) * PLX;    // k pair t4+4 (ic 2t4+8,+9)

#pragma unroll
        for (int tap = 0; tap < 9; tap++) {
            const int kh = tap / 3, kw = tap - 3 * kh;
            const int prow = (warp_n + kh) * BCOLS + g + kw;
            const int fbase = (tap * 8 + warp_m * 2) * 32 + lane;
            const uint4 A0 = Af[fbase];
            const uint4 A1 = Af[fbase + 32];
            const uint32_t* B0 = Bq0 + prow;
            const uint32_t* B1 = Bq1 + prow;
#pragma unroll
            for (int ni = 0; ni < 7; ni++) {
                uint32_t b0 = B0[ni * 8];
                uint32_t b1 = B1[ni * 8];
                mma16(acc[0][ni], A0, b0, b1);
                mma16(acc[1][ni], A1, b0, b1);
            }
        }
    }

    // ---- epilogue
    const int oh = rg * 4 + warp_n;
    if (oh < OHH) {
#pragma unroll
        for (int mi = 0; mi < 2; mi++) {
            const int oc0 = half * 128 + warp_m * 32 + mi * 16 + g;
            const float bv0 = bias[oc0];
            const float bv1 = bias[oc0 + 8];
            float* o0 = out + ((size_t)n * OCH + oc0) * (OHH * OWW) + oh * OWW;
            float* o1 = o0 + 8 * (OHH * OWW);
#pragma unroll
            for (int ni = 0; ni < 7; ni++) {
                const int ow = ni * 8 + 2 * t4;
                if (ow < OWW) {
                    float2 v0 = make_float2(acc[mi][ni][0] + bv0, acc[mi][ni][1] + bv0);
                    float2 v1 = make_float2(acc[mi][ni][2] + bv1, acc[mi][ni][3] + bv1);
                    *(float2*)(o0 + ow) = v0;
                    *(float2*)(o1 + ow) = v1;
                }
            }
        }
    }
}

// ------------------------- launch -------------------------------------------
extern "C" void kernel_launch(void* const* d_in, const int* in_sizes, int n_in,
                              void* d_out, int out_size) {
    const float* x    = (const float*)d_in[0];
    const float* w    = (const float*)d_in[1];
    const float* bias = (const float*)d_in[2];
    float*       out  = (float*)d_out;

    k_init<<<1, 1>>>();
    k_max<<<256, 256>>>(w, OCH * CC * 9);
    k_xh<<<(NN * 64 * HHH * 14 + 255) / 256, 256>>>(x);
    k_quant<<<(2 * NCHUNK * A_WORDS_CHUNK + 255) / 256, 256>>>(w);

    cudaFuncSetAttribute(k_conv, cudaFuncAttributeMaxDynamicSharedMemorySize, SMEM_DYN);
    dim3 grid(2, 14, NN);
    k_conv<<<grid, NTHR, SMEM_DYN>>>(bias, out);

    (void)in_sizes; (void)n_in; (void)out_size;
}

// round 12
// speedup vs baseline: 1.0561x; 1.0561x over previous
#include <cuda_runtime.h>
#include <cuda_fp16.h>
#include <cstdint>

// ---------------------------------------------------------------------------
// TernaryConv2d via mma.sync m16n8k16 (HMMA fp16, fp32 accum) implicit GEMM.
// Warp tile M=64 (4 mtiles): each B operand pair feeds 4 HMMAs -> LDS-light.
// 256-thr CTA (2 warp_m x 4 warp_n rows), 2-stage cp.async pipeline.
// x: [32,128,56,56] f32, w: [256,128,3,3] f32, bias:[256] -> out:[32,256,54,54]
// ---------------------------------------------------------------------------

#define CC    128
#define HHH   56
#define WID   56
#define OCH   256
#define OHH   54
#define OWW   54
#define NN    32

#define NTHR   256
#define ICK    16           // ic per chunk (one k16 HMMA deep)
#define NCHUNK 8
#define BROWS  6            // 4 out rows + 2 halo
#define BCOLS  68           // row stride in half2 words
#define PLX    424          // per-icpair plane stride (424%32=8 -> bank perm 8*t4+g)
#define A_WORDS_CHUNK (9 * 8 * 32 * 4)         // 9216 words = 36864 B
#define A_BYTES_CHUNK (A_WORDS_CHUNK * 4)
#define B_WORDS       (8 * PLX)                // 3392 words = 13568 B
#define STAGE_BYTES   (A_BYTES_CHUNK + B_WORDS * 4)    // 50432
#define SMEM_DYN      (2 * STAGE_BYTES)                // 100864

__device__ __align__(16) uint32_t g_qw[2 * NCHUNK * A_WORDS_CHUNK];
__device__ __align__(16) uint32_t g_xh[NN * 64 * HHH * WID];   // half2 planes
__device__ unsigned g_wmax_bits;

// ------------------------- preprocessing ----------------------------------
__global__ void k_init() { g_wmax_bits = 0u; }

__global__ void k_max(const float* __restrict__ w, int n) {
    float m = 0.f;
    for (int i = blockIdx.x * blockDim.x + threadIdx.x; i < n; i += gridDim.x * blockDim.x)
        m = fmaxf(m, fabsf(w[i]));
#pragma unroll
    for (int o = 16; o > 0; o >>= 1) m = fmaxf(m, __shfl_xor_sync(~0u, m, o));
    __shared__ float sm[32];
    int lane = threadIdx.x & 31, wd = threadIdx.x >> 5;
    if (lane == 0) sm[wd] = m;
    __syncthreads();
    if (threadIdx.x < 32) {
        int nw = (blockDim.x + 31) >> 5;
        m = (threadIdx.x < nw) ? sm[threadIdx.x] : 0.f;
#pragma unroll
        for (int o = 16; o > 0; o >>= 1) m = fmaxf(m, __shfl_xor_sync(~0u, m, o));
        if (threadIdx.x == 0) atomicMax(&g_wmax_bits, __float_as_uint(m));
    }
}

// quantize weights into m16n8k16 A-fragment order, half2-packed:
// word idx = ((half*8+chunk)*72 + tap*8 + mtile)*128 + lane*4 + r
__global__ void k_quant(const float* __restrict__ w) {
    int idx = blockIdx.x * blockDim.x + threadIdx.x;
    if (idx >= 2 * NCHUNK * A_WORDS_CHUNK) return;
    int r     = idx & 3;
    int lane  = (idx >> 2) & 31;
    int f     = idx >> 7;
    int mtile = f & 7;
    int tap   = (f >> 3) % 9;
    int hc    = f / 72;
    int half  = hc >> 3, chunk = hc & 7;
    int g  = lane >> 2, t4 = lane & 3;
    int oc  = half * 128 + mtile * 16 + g + 8 * (r & 1);
    int ic0 = chunk * ICK + 2 * t4 + 8 * (r >> 1);
    float t = 0.05f * __uint_as_float(g_wmax_bits);
    float w0 = w[(oc * CC + ic0) * 9 + tap];
    float w1 = w[(oc * CC + ic0 + 1) * 9 + tap];
    __half h0 = __float2half_rn((w0 > t ? 1.f : 0.f) - (w0 < -t ? 1.f : 0.f));
    __half h1 = __float2half_rn((w1 > t ? 1.f : 0.f) - (w1 < -t ? 1.f : 0.f));
    g_qw[idx] = (uint32_t)__half_as_ushort(h0) | ((uint32_t)__half_as_ushort(h1) << 16);
}

// x -> channel-pair packed half2 planes, vectorized 4 cols/thread
__global__ void k_xh(const float* __restrict__ x) {
    int idx = blockIdx.x * blockDim.x + threadIdx.x;   // over NN*64*HHH*14
    if (idx >= NN * 64 * HHH * 14) return;
    int c4  = idx % 14;
    int h   = (idx / 14) % HHH;
    int icp = (idx / (14 * HHH)) & 63;
    int n   = idx / (14 * HHH * 64);
    const float* p = x + ((size_t)(n * CC + icp * 2) * HHH + h) * WID + c4 * 4;
    float4 a = *(const float4*)p;
    float4 b = *(const float4*)(p + HHH * WID);
    uint4 o;
    o.x = (uint32_t)__half_as_ushort(__float2half_rn(a.x)) | ((uint32_t)__half_as_ushort(__float2half_rn(b.x)) << 16);
    o.y = (uint32_t)__half_as_ushort(__float2half_rn(a.y)) | ((uint32_t)__half_as_ushort(__float2half_rn(b.y)) << 16);
    o.z = (uint32_t)__half_as_ushort(__float2half_rn(a.z)) | ((uint32_t)__half_as_ushort(__float2half_rn(b.z)) << 16);
    o.w = (uint32_t)__half_as_ushort(__float2half_rn(a.w)) | ((uint32_t)__half_as_ushort(__float2half_rn(b.w)) << 16);
    *(uint4*)(g_xh + ((size_t)(n * 64 + icp) * HHH + h) * WID + c4 * 4) = o;
}

// ------------------------- helpers -----------------------------------------
__device__ __forceinline__ void mma16(float* c, const uint4& a, uint32_t b0, uint32_t b1) {
    asm volatile(
        "mma.sync.aligned.m16n8k16.row.col.f32.f16.f16.f32 "
        "{%0,%1,%2,%3}, {%4,%5,%6,%7}, {%8,%9}, {%0,%1,%2,%3};"
        : "+f"(c[0]), "+f"(c[1]), "+f"(c[2]), "+f"(c[3])
        : "r"(a.x), "r"(a.y), "r"(a.z), "r"(a.w), "r"(b0), "r"(b1));
}

__device__ __forceinline__ uint32_t smem_u32(const void* p) {
    uint32_t a;
    asm("{ .reg .u64 t; cvta.to.shared.u64 t, %1; cvt.u32.u64 %0, t; }" : "=r"(a) : "l"(p));
    return a;
}

__device__ __forceinline__ void cpa16(uint32_t dst, const void* src) {
    asm volatile("cp.async.cg.shared.global [%0], [%1], 16;" :: "r"(dst), "l"(src) : "memory");
}
__device__ __forceinline__ void cpa16_p(uint32_t dst, const void* src, int sz) {
    asm volatile("cp.async.cg.shared.global [%0], [%1], 16, %2;"
                 :: "r"(dst), "l"(src), "r"(sz) : "memory");
}

// issue all cp.async for one ic-chunk into stage buffer at smem addr `sbase`
__device__ __forceinline__ void stage_chunk(uint32_t sbase, int chunk, int half,
                                            int rg, int n, int tid) {
    // A: 2304 x 16B, linear, 9 per thread
    const uint4* asrc = (const uint4*)(g_qw + (size_t)(half * NCHUNK + chunk) * A_WORDS_CHUNK);
#pragma unroll
    for (int i = 0; i < 9; i++) {
        int e = i * NTHR + tid;
        cpa16(sbase + e * 16, asrc + e);
    }
    // B: 8 icpair x 6 rows x 14 x 16B; zero-fill rows beyond input (rg=13)
    const uint32_t bdst = sbase + A_BYTES_CHUNK;
#pragma unroll
    for (int it = 0; it < 3; it++) {
        int i = it * NTHR + tid;
        if (i < 8 * BROWS * 14) {
            int c4  = i % 14;
            int row = (i / 14) % BROWS;
            int icp = i / (14 * BROWS);
            int h   = rg * 4 + row;
            const uint32_t* s = g_xh + ((size_t)(n * 64 + chunk * 8 + icp) * HHH + h) * WID + c4 * 4;
            cpa16_p(bdst + (icp * PLX + row * BCOLS + c4 * 4) * 4, s, (h < HHH) ? 16 : 0);
        }
    }
    asm volatile("cp.async.commit_group;" ::: "memory");
}

// ------------------------- conv kernel --------------------------------------
// grid (2 oc-halves, 14 row-groups, 32 n), block 256 (warp_m 0..1, warp_n 0..3)
__global__ __launch_bounds__(NTHR, 1) void k_conv(const float* __restrict__ bias,
                                                  float* __restrict__ out) {
    extern __shared__ char smem[];
    const uint32_t sb = smem_u32(smem);

    const int tid    = threadIdx.x;
    const int wid    = tid >> 5;
    const int lane   = tid & 31;
    const int warp_m = wid & 1;       // 64-oc group (4 mtiles)
    const int warp_n = wid >> 1;      // 0..3 output rows
    const int g      = lane >> 2;
    const int t4     = lane & 3;
    const int half   = blockIdx.x;
    const int rg     = blockIdx.y;
    const int n      = blockIdx.z;

    // one-time zero of both B regions (pad cols + plane pad stay zero)
    for (int s = 0; s < 2; s++) {
        uint32_t* B = (uint32_t*)(smem + s * STAGE_BYTES + A_BYTES_CHUNK);
        for (int i = tid; i < B_WORDS; i += NTHR) B[i] = 0;
    }
    __syncthreads();

    float acc[4][7][4];
#pragma unroll
    for (int mi = 0; mi < 4; mi++)
#pragma unroll
        for (int ni = 0; ni < 7; ni++)
#pragma unroll
            for (int r = 0; r < 4; r++) acc[mi][ni][r] = 0.f;

    stage_chunk(sb, 0, half, rg, n, tid);

    for (int chunk = 0; chunk < NCHUNK; chunk++) {
        asm volatile("cp.async.wait_group 0;" ::: "memory");
        __syncthreads();
        if (chunk + 1 < NCHUNK)
            stage_chunk(sb + ((chunk + 1) & 1) * STAGE_BYTES, chunk + 1, half, rg, n, tid);

        const char*     stg = smem + (chunk & 1) * STAGE_BYTES;
        const uint4*    Af  = (const uint4*)stg;
        const uint32_t* Bs  = (const uint32_t*)(stg + A_BYTES_CHUNK);
        const uint32_t* Bq0 = Bs + t4 * PLX;          // k pair t4
        const uint32_t* Bq1 = Bs + (t4 + 4) * PLX;    // k pair t4+4

#pragma unroll
        for (int tap = 0; tap < 9; tap++) {
            const int kh = tap / 3, kw = tap - 3 * kh;
            const int prow = (warp_n + kh) * BCOLS + g + kw;
            const int fbase = (tap * 8 + warp_m * 4) * 32 + lane;
            const uint4 A0 = Af[fbase];
            const uint4 A1 = Af[fbase + 32];
            const uint4 A2 = Af[fbase + 64];
            const uint4 A3 = Af[fbase + 96];
            const uint32_t* B0 = Bq0 + prow;
            const uint32_t* B1 = Bq1 + prow;
#pragma unroll
            for (int ni = 0; ni < 7; ni++) {
                uint32_t b0 = B0[ni * 8];
                uint32_t b1 = B1[ni * 8];
                mma16(acc[0][ni], A0, b0, b1);
                mma16(acc[1][ni], A1, b0, b1);
                mma16(acc[2][ni], A2, b0, b1);
                mma16(acc[3][ni], A3, b0, b1);
            }
        }
    }

    // ---- epilogue
    const int oh = rg * 4 + warp_n;
    if (oh < OHH) {
#pragma unroll
        for (int mi = 0; mi < 4; mi++) {
            const int oc0 = half * 128 + warp_m * 64 + mi * 16 + g;
            const float bv0 = bias[oc0];
            const float bv1 = bias[oc0 + 8];
            float* o0 = out + ((size_t)n * OCH + oc0) * (OHH * OWW) + oh * OWW;
            float* o1 = o0 + 8 * (OHH * OWW);
#pragma unroll
            for (int ni = 0; ni < 7; ni++) {
                const int ow = ni * 8 + 2 * t4;
                if (ow < OWW) {
                    float2 v0 = make_float2(acc[mi][ni][0] + bv0, acc[mi][ni][1] + bv0);
                    float2 v1 = make_float2(acc[mi][ni][2] + bv1, acc[mi][ni][3] + bv1);
                    *(float2*)(o0 + ow) = v0;
                    *(float2*)(o1 + ow) = v1;
                }
            }
        }
    }
}

// ------------------------- launch -------------------------------------------
extern "C" void kernel_launch(void* const* d_in, const int* in_sizes, int n_in,
                              void* d_out, int out_size) {
    const float* x    = (const float*)d_in[0];
    const float* w    = (const float*)d_in[1];
    const float* bias = (const float*)d_in[2];
    float*       out  = (float*)d_out;

    k_init<<<1, 1>>>();
    k_max<<<256, 256>>>(w, OCH * CC * 9);
    k_xh<<<(NN * 64 * HHH * 14 + 255) / 256, 256>>>(x);
    k_quant<<<(2 * NCHUNK * A_WORDS_CHUNK + 255) / 256, 256>>>(w);

    cudaFuncSetAttribute(k_conv, cudaFuncAttributeMaxDynamicSharedMemorySize, SMEM_DYN);
    dim3 grid(2, 14, NN);
    k_conv<<<grid, NTHR, SMEM_DYN>>>(bias, out);

    (void)in_sizes; (void)n_in; (void)out_size;
}

// round 13
// speedup vs baseline: 1.1104x; 1.0515x over previous
#include <cuda_runtime.h>
#include <cuda_fp16.h>
#include <cstdint>

// ---------------------------------------------------------------------------
// TernaryConv2d via mma.sync m16n8k16 (HMMA fp16, fp32 accum) implicit GEMM.
// Warp tile M=64 (4 mtiles/warp): one B pair feeds 4 HMMAs. 128-thr CTAs,
// 2 CTAs/SM co-residency, 2-stage cp.async pipeline, fine-grained grid.
// x: [32,128,56,56] f32, w: [256,128,3,3] f32, bias:[256] -> out:[32,256,54,54]
// ---------------------------------------------------------------------------

#define CC    128
#define HHH   56
#define WID   56
#define OCH   256
#define OHH   54
#define OWW   54
#define NN    32

#define NTHR   128
#define ICK    16           // ic per chunk (one k16 HMMA deep)
#define NCHUNK 8
#define BROWS  4            // 2 out rows + 2 halo (always in-bounds: rg<=26)
#define BCOLS  68           // row stride in half2 words
#define PLX    280          // per-icpair plane stride (280%32=24 -> bank perm 24*t4+g)
#define A_WORDS_CHUNK (9 * 8 * 32 * 4)         // 9216 words = 36864 B
#define A_BYTES_CHUNK (A_WORDS_CHUNK * 4)
#define B_WORDS       (8 * PLX)                // 2240 words = 8960 B
#define STAGE_BYTES   (A_BYTES_CHUNK + B_WORDS * 4)    // 45824
#define SMEM_DYN      (2 * STAGE_BYTES)                // 91648 (x2 CTAs = 183KB/SM)

__device__ __align__(16) uint32_t g_qw[2 * NCHUNK * A_WORDS_CHUNK];
__device__ __align__(16) uint32_t g_xh[NN * 64 * HHH * WID];   // half2 planes
__device__ unsigned g_wmax_bits;

// ------------------------- preprocessing ----------------------------------
__global__ void k_init() { g_wmax_bits = 0u; }

__global__ void k_max(const float* __restrict__ w, int n) {
    float m = 0.f;
    for (int i = blockIdx.x * blockDim.x + threadIdx.x; i < n; i += gridDim.x * blockDim.x)
        m = fmaxf(m, fabsf(w[i]));
#pragma unroll
    for (int o = 16; o > 0; o >>= 1) m = fmaxf(m, __shfl_xor_sync(~0u, m, o));
    __shared__ float sm[32];
    int lane = threadIdx.x & 31, wd = threadIdx.x >> 5;
    if (lane == 0) sm[wd] = m;
    __syncthreads();
    if (threadIdx.x < 32) {
        int nw = (blockDim.x + 31) >> 5;
        m = (threadIdx.x < nw) ? sm[threadIdx.x] : 0.f;
#pragma unroll
        for (int o = 16; o > 0; o >>= 1) m = fmaxf(m, __shfl_xor_sync(~0u, m, o));
        if (threadIdx.x == 0) atomicMax(&g_wmax_bits, __float_as_uint(m));
    }
}

// quantize weights into m16n8k16 A-fragment order, half2-packed:
// word idx = ((half*8+chunk)*72 + tap*8 + mtile)*128 + lane*4 + r
__global__ void k_quant(const float* __restrict__ w) {
    int idx = blockIdx.x * blockDim.x + threadIdx.x;
    if (idx >= 2 * NCHUNK * A_WORDS_CHUNK) return;
    int r     = idx & 3;
    int lane  = (idx >> 2) & 31;
    int f     = idx >> 7;
    int mtile = f & 7;
    int tap   = (f >> 3) % 9;
    int hc    = f / 72;
    int half  = hc >> 3, chunk = hc & 7;
    int g  = lane >> 2, t4 = lane & 3;
    int oc  = half * 128 + mtile * 16 + g + 8 * (r & 1);
    int ic0 = chunk * ICK + 2 * t4 + 8 * (r >> 1);
    float t = 0.05f * __uint_as_float(g_wmax_bits);
    float w0 = w[(oc * CC + ic0) * 9 + tap];
    float w1 = w[(oc * CC + ic0 + 1) * 9 + tap];
    __half h0 = __float2half_rn((w0 > t ? 1.f : 0.f) - (w0 < -t ? 1.f : 0.f));
    __half h1 = __float2half_rn((w1 > t ? 1.f : 0.f) - (w1 < -t ? 1.f : 0.f));
    g_qw[idx] = (uint32_t)__half_as_ushort(h0) | ((uint32_t)__half_as_ushort(h1) << 16);
}

// x -> channel-pair packed half2 planes, vectorized 4 cols/thread
__global__ void k_xh(const float* __restrict__ x) {
    int idx = blockIdx.x * blockDim.x + threadIdx.x;   // over NN*64*HHH*14
    if (idx >= NN * 64 * HHH * 14) return;
    int c4  = idx % 14;
    int h   = (idx / 14) % HHH;
    int icp = (idx / (14 * HHH)) & 63;
    int n   = idx / (14 * HHH * 64);
    const float* p = x + ((size_t)(n * CC + icp * 2) * HHH + h) * WID + c4 * 4;
    float4 a = *(const float4*)p;
    float4 b = *(const float4*)(p + HHH * WID);
    uint4 o;
    o.x = (uint32_t)__half_as_ushort(__float2half_rn(a.x)) | ((uint32_t)__half_as_ushort(__float2half_rn(b.x)) << 16);
    o.y = (uint32_t)__half_as_ushort(__float2half_rn(a.y)) | ((uint32_t)__half_as_ushort(__float2half_rn(b.y)) << 16);
    o.z = (uint32_t)__half_as_ushort(__float2half_rn(a.z)) | ((uint32_t)__half_as_ushort(__float2half_rn(b.z)) << 16);
    o.w = (uint32_t)__half_as_ushort(__float2half_rn(a.w)) | ((uint32_t)__half_as_ushort(__float2half_rn(b.w)) << 16);
    *(uint4*)(g_xh + ((size_t)(n * 64 + icp) * HHH + h) * WID + c4 * 4) = o;
}

// ------------------------- helpers -----------------------------------------
__device__ __forceinline__ void mma16(float* c, const uint4& a, uint32_t b0, uint32_t b1) {
    asm volatile(
        "mma.sync.aligned.m16n8k16.row.col.f32.f16.f16.f32 "
        "{%0,%1,%2,%3}, {%4,%5,%6,%7}, {%8,%9}, {%0,%1,%2,%3};"
        : "+f"(c[0]), "+f"(c[1]), "+f"(c[2]), "+f"(c[3])
        : "r"(a.x), "r"(a.y), "r"(a.z), "r"(a.w), "r"(b0), "r"(b1));
}

__device__ __forceinline__ uint32_t smem_u32(const void* p) {
    uint32_t a;
    asm("{ .reg .u64 t; cvta.to.shared.u64 t, %1; cvt.u32.u64 %0, t; }" : "=r"(a) : "l"(p));
    return a;
}

__device__ __forceinline__ void cpa16(uint32_t dst, const void* src) {
    asm volatile("cp.async.cg.shared.global [%0], [%1], 16;" :: "r"(dst), "l"(src) : "memory");
}

// issue all cp.async for one ic-chunk into stage buffer at smem addr `sbase`
__device__ __forceinline__ void stage_chunk(uint32_t sbase, int chunk, int half,
                                            int rg, int n, int tid) {
    // A: 2304 x 16B, linear, 18 per thread
    const uint4* asrc = (const uint4*)(g_qw + (size_t)(half * NCHUNK + chunk) * A_WORDS_CHUNK);
#pragma unroll
    for (int i = 0; i < 18; i++) {
        int e = i * NTHR + tid;
        cpa16(sbase + e * 16, asrc + e);
    }
    // B: 8 icpair x 4 rows x 14 x 16B = 448 copies; rows always in-bounds
    const uint32_t bdst = sbase + A_BYTES_CHUNK;
#pragma unroll
    for (int it = 0; it < 4; it++) {
        int i = it * NTHR + tid;
        if (i < 8 * BROWS * 14) {
            int c4  = i % 14;
            int row = (i / 14) % BROWS;
            int icp = i / (14 * BROWS);
            const uint32_t* s = g_xh + ((size_t)(n * 64 + chunk * 8 + icp) * HHH
                                        + (rg * 2 + row)) * WID + c4 * 4;
            cpa16(bdst + (icp * PLX + row * BCOLS + c4 * 4) * 4, s);
        }
    }
    asm volatile("cp.async.commit_group;" ::: "memory");
}

// ------------------------- conv kernel --------------------------------------
// grid (2 oc-halves, 27 row-groups, 32 n), block 128 (warp_m 0..1, warp_n 0..1)
__global__ __launch_bounds__(NTHR, 2) void k_conv(const float* __restrict__ bias,
                                                  float* __restrict__ out) {
    extern __shared__ char smem[];
    const uint32_t sb = smem_u32(smem);

    const int tid    = threadIdx.x;
    const int wid    = tid >> 5;
    const int lane   = tid & 31;
    const int warp_m = wid & 1;       // 64-oc group (4 mtiles)
    const int warp_n = wid >> 1;      // 0..1 output rows
    const int g      = lane >> 2;
    const int t4     = lane & 3;
    const int half   = blockIdx.x;
    const int rg     = blockIdx.y;
    const int n      = blockIdx.z;

    // one-time zero of both B regions (pad cols + plane pad stay zero)
    for (int s = 0; s < 2; s++) {
        uint32_t* B = (uint32_t*)(smem + s * STAGE_BYTES + A_BYTES_CHUNK);
        for (int i = tid; i < B_WORDS; i += NTHR) B[i] = 0;
    }
    __syncthreads();

    float acc[4][7][4];
#pragma unroll
    for (int mi = 0; mi < 4; mi++)
#pragma unroll
        for (int ni = 0; ni < 7; ni++)
#pragma unroll
            for (int r = 0; r < 4; r++) acc[mi][ni][r] = 0.f;

    stage_chunk(sb, 0, half, rg, n, tid);

    for (int chunk = 0; chunk < NCHUNK; chunk++) {
        asm volatile("cp.async.wait_group 0;" ::: "memory");
        __syncthreads();
        if (chunk + 1 < NCHUNK)
            stage_chunk(sb + ((chunk + 1) & 1) * STAGE_BYTES, chunk + 1, half, rg, n, tid);

        const char*     stg = smem + (chunk & 1) * STAGE_BYTES;
        const uint4*    Af  = (const uint4*)stg;
        const uint32_t* Bs  = (const uint32_t*)(stg + A_BYTES_CHUNK);
        const uint32_t* Bq0 = Bs + t4 * PLX;          // k pair t4
        const uint32_t* Bq1 = Bs + (t4 + 4) * PLX;    // k pair t4+4

#pragma unroll
        for (int tap = 0; tap < 9; tap++) {
            const int kh = tap / 3, kw = tap - 3 * kh;
            const int prow = (warp_n + kh) * BCOLS + g + kw;
            const int fbase = (tap * 8 + warp_m * 4) * 32 + lane;
            const uint4 A0 = Af[fbase];
            const uint4 A1 = Af[fbase + 32];
            const uint4 A2 = Af[fbase + 64];
            const uint4 A3 = Af[fbase + 96];
            const uint32_t* B0 = Bq0 + prow;
            const uint32_t* B1 = Bq1 + prow;
#pragma unroll
            for (int ni = 0; ni < 7; ni++) {
                uint32_t b0 = B0[ni * 8];
                uint32_t b1 = B1[ni * 8];
                mma16(acc[0][ni], A0, b0, b1);
                mma16(acc[1][ni], A1, b0, b1);
                mma16(acc[2][ni], A2, b0, b1);
                mma16(acc[3][ni], A3, b0, b1);
            }
        }
    }

    // ---- epilogue (oh = rg*2 + warp_n, always < 54)
    const int oh = rg * 2 + warp_n;
#pragma unroll
    for (int mi = 0; mi < 4; mi++) {
        const int oc0 = half * 128 + warp_m * 64 + mi * 16 + g;
        const float bv0 = bias[oc0];
        const float bv1 = bias[oc0 + 8];
        float* o0 = out + ((size_t)n * OCH + oc0) * (OHH * OWW) + oh * OWW;
        float* o1 = o0 + 8 * (OHH * OWW);
#pragma unroll
        for (int ni = 0; ni < 7; ni++) {
            const int ow = ni * 8 + 2 * t4;
            if (ow < OWW) {
                float2 v0 = make_float2(acc[mi][ni][0] + bv0, acc[mi][ni][1] + bv0);
                float2 v1 = make_float2(acc[mi][ni][2] + bv1, acc[mi][ni][3] + bv1);
                *(float2*)(o0 + ow) = v0;
                *(float2*)(o1 + ow) = v1;
            }
        }
    }
}

// ------------------------- launch -------------------------------------------
extern "C" void kernel_launch(void* const* d_in, const int* in_sizes, int n_in,
                              void* d_out, int out_size) {
    const float* x    = (const float*)d_in[0];
    const float* w    = (const float*)d_in[1];
    const float* bias = (const float*)d_in[2];
    float*       out  = (float*)d_out;

    k_init<<<1, 1>>>();
    k_max<<<256, 256>>>(w, OCH * CC * 9);
    k_xh<<<(NN * 64 * HHH * 14 + 255) / 256, 256>>>(x);
    k_quant<<<(2 * NCHUNK * A_WORDS_CHUNK + 255) / 256, 256>>>(w);

    cudaFuncSetAttribute(k_conv, cudaFuncAttributeMaxDynamicSharedMemorySize, SMEM_DYN);
    dim3 grid(2, 27, NN);
    k_conv<<<grid, NTHR, SMEM_DYN>>>(bias, out);

    (void)in_sizes; (void)n_in; (void)out_size;
}